// round 4
// baseline (speedup 1.0000x reference)
#include <cuda_runtime.h>
#include <math.h>

#define BB 8
#define CC 64
#define NN 256
#define M1 20
#define M2 20
#define RR 40
#define MODES 800
#define LL 3
#define FCN 128
#define BP 264          // B-matrix smem row pitch (words)
#define FP 260          // F (A) matrix pitch in stage1
#define AP 68           // A-matrix smem row pitch

// ---------------- device scratch ----------------
__device__ float g_h[BB * CC * NN * NN];
__device__ float g_t1[BB * CC * RR * NN];
__device__ float g_spec[MODES * BB * CC];
__device__ float g_spec2[BB * CC * MODES];
__device__ float g_t2[BB * CC * NN * M2];
__device__ float g_Wm[LL * MODES * CC * CC];
__device__ float g_F1[RR * NN];
__device__ float g_F2[M2 * NN];
__device__ float g_G1[NN * RR];
__device__ float g_G2[NN * M2];

// ---------------- helpers ----------------
__device__ __forceinline__ unsigned f2tf(float f) {
    unsigned u; asm("cvt.rna.tf32.f32 %0,%1;" : "=r"(u) : "f"(f)); return u;
}
__device__ __forceinline__ void split_tf(float v, unsigned& hi, unsigned& lo) {
    unsigned h = f2tf(v);
    hi = h;
    lo = f2tf(v - __uint_as_float(h));
}
__device__ __forceinline__ void mma8(float& d0, float& d1, float& d2, float& d3,
                                     unsigned a0, unsigned a1, unsigned a2, unsigned a3,
                                     unsigned b0, unsigned b1) {
    asm("mma.sync.aligned.m16n8k8.row.col.f32.tf32.tf32.f32 "
        "{%0,%1,%2,%3},{%4,%5,%6,%7},{%8,%9},{%0,%1,%2,%3};"
        : "+f"(d0), "+f"(d1), "+f"(d2), "+f"(d3)
        : "r"(a0), "r"(a1), "r"(a2), "r"(a3), "r"(b0), "r"(b1));
}
// 3xTF32 compensated MMA: hi*hi + hi*lo + lo*hi
#define MMA3(ACC, AH0,AH1,AH2,AH3, AL0,AL1,AL2,AL3, BH0,BH1, BL0,BL1)             \
    do {                                                                           \
        mma8(ACC[0],ACC[1],ACC[2],ACC[3], AH0,AH1,AH2,AH3, BL0,BL1);               \
        mma8(ACC[0],ACC[1],ACC[2],ACC[3], AL0,AL1,AL2,AL3, BH0,BH1);               \
        mma8(ACC[0],ACC[1],ACC[2],ACC[3], AH0,AH1,AH2,AH3, BH0,BH1);               \
    } while (0)

__device__ __forceinline__ float ftanh(float x) {
    float e = __expf(2.f * x);
    return 1.f - __fdividef(2.f, e + 1.f);
}

// ---------------- DCT basis tables ----------------
__global__ void k_init() {
    int x = blockIdx.x, t = threadIdx.x;
    if (t < RR) {
        int k = (t < M1) ? t : (216 + t);
        int m = (k * x) % 510;
        float cv = (float)cospi((double)m / 255.0);
        float cx = (x == 0 || x == 255) ? 1.f : 2.f;
        g_F1[t * NN + x] = cx * cv;
        float ck = (k == 0 || k == 255) ? 1.f : 2.f;
        g_G1[x * RR + t] = ck * cv;
    }
    if (t < M2) {
        int m = (t * x) % 510;
        float cv = (float)cospi((double)m / 255.0);
        float cy = (x == 0 || x == 255) ? 1.f : 2.f;
        g_F2[t * NN + x] = cy * cv;
        float cs = (t == 0) ? 1.f : 2.f;
        g_G2[x * M2 + t] = cs * cv;
    }
}

// ---------------- spectral weight transpose ----------------
__global__ void k_wtrans(const float* __restrict__ w1, const float* __restrict__ w2) {
    __shared__ float tile[32][33];
    int l = blockIdx.z >> 1, half = blockIdx.z & 1;
    const float* src = (half ? w2 : w1) + (size_t)l * CC * CC * (M1 * M2);
    float* dst = g_Wm + ((size_t)l * MODES + half * 400) * (CC * CC);
    int col = blockIdx.x * 32 + threadIdx.x;
    int row = blockIdx.y * 32 + threadIdx.y;
    if (col < 400) tile[threadIdx.y][threadIdx.x] = src[(size_t)row * 400 + col];
    __syncthreads();
    int drow = blockIdx.x * 32 + threadIdx.y;
    int dcol = blockIdx.y * 32 + threadIdx.x;
    if (drow < 400) dst[(size_t)drow * 4096 + dcol] = tile[threadIdx.x][threadIdx.y];
}

// ---------------- fc0 ----------------
__global__ void k_fc0(const float* __restrict__ x, const float* __restrict__ w,
                      const float* __restrict__ bias) {
    __shared__ float sw[3][CC];
    __shared__ float sb[CC];
    int xi = blockIdx.x, b = blockIdx.y, y = threadIdx.x;
    if (y < CC) { sw[0][y] = w[y]; sw[1][y] = w[CC + y]; sw[2][y] = w[2 * CC + y]; sb[y] = bias[y]; }
    __syncthreads();
    const float* xp = x + (((size_t)b * NN + xi) * NN + y) * 3;
    float d0 = xp[0], d1 = xp[1], d2 = xp[2];
    float* hp = g_h + ((size_t)(b * CC) * NN + xi) * NN + y;
#pragma unroll
    for (int c = 0; c < CC; c++)
        hp[(size_t)c * (NN * NN)] = sb[c] + d0 * sw[0][c] + d1 * sw[1][c] + d2 * sw[2][c];
}

// ---------------- forward DCT stage 1 (3xTF32): t1 = F1(40x256) * H(256x256) per bc ---------
__global__ __launch_bounds__(384) void k_stage1_mma() {
    extern __shared__ unsigned sm[];
    unsigned* sFh = sm;                    // [48][FP]
    unsigned* sFl = sFh + 48 * FP;
    unsigned* sHh = sFl + 48 * FP;         // [32][BP]
    unsigned* sHl = sHh + 32 * BP;
    int bc = blockIdx.x, tid = threadIdx.x;
    int wid = tid >> 5, lane = tid & 31, gid = lane >> 2, tig = lane & 3;
    int mt = wid % 3, ng = wid / 3;
    int rbase = mt * 16, ybase = ng * 64;

    for (int idx = tid; idx < 48 * NN; idx += 384) {
        int r = idx >> 8, x = idx & 255;
        float v = (r < RR) ? g_F1[r * NN + x] : 0.f;
        split_tf(v, sFh[r * FP + x], sFl[r * FP + x]);
    }
    float acc[8][4];
#pragma unroll
    for (int i = 0; i < 8; i++) { acc[i][0] = acc[i][1] = acc[i][2] = acc[i][3] = 0.f; }

    const float4* hp = (const float4*)(g_h + (size_t)bc * (NN * NN));
    for (int ch = 0; ch < 8; ch++) {
        __syncthreads();
        for (int idx = tid; idx < 32 * 64; idx += 384) {
            int row = idx >> 6, q = idx & 63;
            float4 v = hp[(ch * 32 + row) * 64 + q];
            unsigned* dh = &sHh[row * BP + q * 4];
            unsigned* dl = &sHl[row * BP + q * 4];
            split_tf(v.x, dh[0], dl[0]); split_tf(v.y, dh[1], dl[1]);
            split_tf(v.z, dh[2], dl[2]); split_tf(v.w, dh[3], dl[3]);
        }
        __syncthreads();
#pragma unroll
        for (int ks = 0; ks < 4; ks++) {
            int k0 = ks * 8;
            int ca = ch * 32 + k0 + tig;
            unsigned ah0 = sFh[(rbase + gid) * FP + ca];
            unsigned ah1 = sFh[(rbase + gid + 8) * FP + ca];
            unsigned ah2 = sFh[(rbase + gid) * FP + ca + 4];
            unsigned ah3 = sFh[(rbase + gid + 8) * FP + ca + 4];
            unsigned al0 = sFl[(rbase + gid) * FP + ca];
            unsigned al1 = sFl[(rbase + gid + 8) * FP + ca];
            unsigned al2 = sFl[(rbase + gid) * FP + ca + 4];
            unsigned al3 = sFl[(rbase + gid + 8) * FP + ca + 4];
#pragma unroll
            for (int nt = 0; nt < 8; nt++) {
                int n = ybase + nt * 8 + gid;
                unsigned bh0 = sHh[(k0 + tig) * BP + n];
                unsigned bh1 = sHh[(k0 + tig + 4) * BP + n];
                unsigned bl0 = sHl[(k0 + tig) * BP + n];
                unsigned bl1 = sHl[(k0 + tig + 4) * BP + n];
                MMA3(acc[nt], ah0,ah1,ah2,ah3, al0,al1,al2,al3, bh0,bh1, bl0,bl1);
            }
        }
    }
    float* tp = g_t1 + (size_t)bc * (RR * NN);
    int r0 = rbase + gid, r1 = r0 + 8;
#pragma unroll
    for (int nt = 0; nt < 8; nt++) {
        int y0 = ybase + nt * 8 + tig * 2;
        *(float2*)&tp[r0 * NN + y0] = make_float2(acc[nt][0], acc[nt][1]);
        if (r1 < RR) *(float2*)&tp[r1 * NN + y0] = make_float2(acc[nt][2], acc[nt][3]);
    }
}

// ---------------- forward DCT stage 2 (exact fp32) ----------------
__global__ __launch_bounds__(256) void k_stage2() {
    __shared__ float4 sT[RR * 64];
    int bc = blockIdx.x, t = threadIdx.x;
    const float4* t14 = (const float4*)(g_t1 + (size_t)bc * (RR * NN));
    for (int i = t; i < RR * 64; i += 256) sT[i] = t14[i];
    __syncthreads();
    if (t < 200) {
        int a = t / 5, q = t % 5;
        float4 acc = make_float4(0.f, 0.f, 0.f, 0.f);
        const float4* F24 = (const float4*)g_F2;
        for (int y4 = 0; y4 < 64; y4++) {
            float4 tv = sT[a * 64 + y4];
            float4 f0 = __ldg(&F24[(4 * q + 0) * 64 + y4]);
            float4 f1 = __ldg(&F24[(4 * q + 1) * 64 + y4]);
            float4 f2 = __ldg(&F24[(4 * q + 2) * 64 + y4]);
            float4 f3 = __ldg(&F24[(4 * q + 3) * 64 + y4]);
            acc.x += tv.x * f0.x + tv.y * f0.y + tv.z * f0.z + tv.w * f0.w;
            acc.y += tv.x * f1.x + tv.y * f1.y + tv.z * f1.z + tv.w * f1.w;
            acc.z += tv.x * f2.x + tv.y * f2.y + tv.z * f2.z + tv.w * f2.w;
            acc.w += tv.x * f3.x + tv.y * f3.y + tv.z * f3.z + tv.w * f3.w;
        }
        int m0 = a * M2 + 4 * q;
        g_spec[(size_t)(m0 + 0) * (BB * CC) + bc] = acc.x;
        g_spec[(size_t)(m0 + 1) * (BB * CC) + bc] = acc.y;
        g_spec[(size_t)(m0 + 2) * (BB * CC) + bc] = acc.z;
        g_spec[(size_t)(m0 + 3) * (BB * CC) + bc] = acc.w;
    }
}

// ---------------- per-mode channel mix (exact fp32) ----------------
__global__ __launch_bounds__(256) void k_mix(int l) {
    __shared__ float sW[CC * CC];
    __shared__ float sS[BB * CC];
    int m = blockIdx.x, t = threadIdx.x;
    const float* Wp = g_Wm + ((size_t)l * MODES + m) * (CC * CC);
    for (int i = t; i < CC * CC; i += 256) sW[i] = Wp[i];
    for (int i = t; i < BB * CC; i += 256) sS[i] = g_spec[(size_t)m * (BB * CC) + i];
    __syncthreads();
#pragma unroll
    for (int k = 0; k < 2; k++) {
        int idx = t + k * 256;
        int b = idx >> 6, o = idx & 63;
        float acc = 0.f;
#pragma unroll
        for (int i = 0; i < CC; i++) acc += sS[b * CC + i] * sW[i * CC + o];
        g_spec2[(size_t)(b * CC + o) * MODES + m] = acc;
    }
}

// ---------------- inverse stage 1 (exact fp32) ----------------
__global__ __launch_bounds__(256) void k_istage1() {
    __shared__ float sS[MODES];
    int bo = blockIdx.x, x = threadIdx.x;
    for (int i = x; i < MODES; i += 256) sS[i] = g_spec2[(size_t)bo * MODES + i];
    __syncthreads();
    float g1r[RR];
    const float4* gp = (const float4*)(g_G1 + x * RR);
#pragma unroll
    for (int j = 0; j < RR / 4; j++) {
        float4 v = gp[j];
        g1r[4 * j] = v.x; g1r[4 * j + 1] = v.y; g1r[4 * j + 2] = v.z; g1r[4 * j + 3] = v.w;
    }
    float acc[M2];
#pragma unroll
    for (int s = 0; s < M2; s++) acc[s] = 0.f;
#pragma unroll 4
    for (int r = 0; r < RR; r++) {
        float g = g1r[r];
#pragma unroll
        for (int s = 0; s < M2; s++) acc[s] += g * sS[r * M2 + s];
    }
    float* tp = g_t2 + ((size_t)bo * NN + x) * M2;
#pragma unroll
    for (int s = 0; s < M2; s++) tp[s] = acc[s];
}

// ---------------- fused layer update (3xTF32, in place) ----------------
// OUT(64x256) = CW(64x64)*H(64x256) + T2(64x24)*G2T(24x256) + bias, [tanh]
__global__ __launch_bounds__(512) void k_ilayer_mma(const float* __restrict__ conv_w,
                                                    const float* __restrict__ conv_b,
                                                    int l, int do_tanh) {
    extern __shared__ unsigned sm[];
    unsigned* sGh  = sm;                    // [24][BP]
    unsigned* sGl  = sGh + 24 * BP;
    unsigned* sA1h = sGl + 24 * BP;         // [64][AP]
    unsigned* sA1l = sA1h + 64 * AP;
    unsigned* sA2h = sA1l + 64 * AP;        // [64][28]
    unsigned* sA2l = sA2h + 64 * 28;
    unsigned* sHh  = sA2l + 64 * 28;        // [32][BP]
    unsigned* sHl  = sHh + 32 * BP;
    int x = blockIdx.x, b = blockIdx.y, tid = threadIdx.x;
    int wid = tid >> 5, lane = tid & 31, gid = lane >> 2, tig = lane & 3;
    int mt = wid & 3, nh = wid >> 2;        // mt 0..3, nh 0..3
    int obase = mt * 16, ybase = nh * 64;

    const float* cw = conv_w + (size_t)l * CC * CC;
    for (int idx = tid; idx < 64 * AP; idx += 512) {
        int o = idx / AP, i = idx % AP;
        float v = (i < 64) ? cw[o * 64 + i] : 0.f;
        split_tf(v, sA1h[idx], sA1l[idx]);
    }
    for (int idx = tid; idx < 64 * 28; idx += 512) {
        int o = idx / 28, s = idx % 28;
        float v = (s < 20) ? g_t2[(((size_t)(b * 64 + o)) * NN + x) * M2 + s] : 0.f;
        split_tf(v, sA2h[idx], sA2l[idx]);
    }
    for (int idx = tid; idx < 24 * NN; idx += 512) {
        int s = idx >> 8, y = idx & 255;
        float v = (s < 20) ? g_G2[y * M2 + s] : 0.f;
        split_tf(v, sGh[s * BP + y], sGl[s * BP + y]);
    }
    __syncthreads();

    float bias0 = __ldg(&conv_b[l * 64 + obase + gid]);
    float bias1 = __ldg(&conv_b[l * 64 + obase + gid + 8]);
    float acc[8][4];
#pragma unroll
    for (int nt = 0; nt < 8; nt++) { acc[nt][0] = acc[nt][1] = bias0; acc[nt][2] = acc[nt][3] = bias1; }

    // DCT term: K = 24
#pragma unroll
    for (int ks = 0; ks < 3; ks++) {
        int k0 = ks * 8;
        unsigned ah0 = sA2h[(obase + gid) * 28 + k0 + tig];
        unsigned ah1 = sA2h[(obase + gid + 8) * 28 + k0 + tig];
        unsigned ah2 = sA2h[(obase + gid) * 28 + k0 + tig + 4];
        unsigned ah3 = sA2h[(obase + gid + 8) * 28 + k0 + tig + 4];
        unsigned al0 = sA2l[(obase + gid) * 28 + k0 + tig];
        unsigned al1 = sA2l[(obase + gid + 8) * 28 + k0 + tig];
        unsigned al2 = sA2l[(obase + gid) * 28 + k0 + tig + 4];
        unsigned al3 = sA2l[(obase + gid + 8) * 28 + k0 + tig + 4];
#pragma unroll
        for (int nt = 0; nt < 8; nt++) {
            int n = ybase + nt * 8 + gid;
            unsigned bh0 = sGh[(k0 + tig) * BP + n];
            unsigned bh1 = sGh[(k0 + tig + 4) * BP + n];
            unsigned bl0 = sGl[(k0 + tig) * BP + n];
            unsigned bl1 = sGl[(k0 + tig + 4) * BP + n];
            MMA3(acc[nt], ah0,ah1,ah2,ah3, al0,al1,al2,al3, bh0,bh1, bl0,bl1);
        }
    }

    // conv term: K = 64 in two chunks of 32
    for (int hc = 0; hc < 2; hc++) {
        __syncthreads();
        for (int idx = tid; idx < 32 * 64; idx += 512) {
            int i = idx >> 6, q = idx & 63;
            float4 v = *(const float4*)&g_h[(((size_t)(b * 64 + hc * 32 + i)) * NN + x) * NN + q * 4];
            unsigned* dh = &sHh[i * BP + q * 4];
            unsigned* dl = &sHl[i * BP + q * 4];
            split_tf(v.x, dh[0], dl[0]); split_tf(v.y, dh[1], dl[1]);
            split_tf(v.z, dh[2], dl[2]); split_tf(v.w, dh[3], dl[3]);
        }
        __syncthreads();
#pragma unroll
        for (int ks = 0; ks < 4; ks++) {
            int k0 = ks * 8;
            int ca = hc * 32 + k0 + tig;
            unsigned ah0 = sA1h[(obase + gid) * AP + ca];
            unsigned ah1 = sA1h[(obase + gid + 8) * AP + ca];
            unsigned ah2 = sA1h[(obase + gid) * AP + ca + 4];
            unsigned ah3 = sA1h[(obase + gid + 8) * AP + ca + 4];
            unsigned al0 = sA1l[(obase + gid) * AP + ca];
            unsigned al1 = sA1l[(obase + gid + 8) * AP + ca];
            unsigned al2 = sA1l[(obase + gid) * AP + ca + 4];
            unsigned al3 = sA1l[(obase + gid + 8) * AP + ca + 4];
#pragma unroll
            for (int nt = 0; nt < 8; nt++) {
                int n = ybase + nt * 8 + gid;
                unsigned bh0 = sHh[(k0 + tig) * BP + n];
                unsigned bh1 = sHh[(k0 + tig + 4) * BP + n];
                unsigned bl0 = sHl[(k0 + tig) * BP + n];
                unsigned bl1 = sHl[(k0 + tig + 4) * BP + n];
                MMA3(acc[nt], ah0,ah1,ah2,ah3, al0,al1,al2,al3, bh0,bh1, bl0,bl1);
            }
        }
    }

    int r0 = obase + gid, r1 = r0 + 8;
    float* h0 = &g_h[(((size_t)(b * 64 + r0)) * NN + x) * NN];
    float* h1 = &g_h[(((size_t)(b * 64 + r1)) * NN + x) * NN];
#pragma unroll
    for (int nt = 0; nt < 8; nt++) {
        int y0 = ybase + nt * 8 + tig * 2;
        float d0 = acc[nt][0], d1 = acc[nt][1], d2 = acc[nt][2], d3 = acc[nt][3];
        if (do_tanh) { d0 = ftanh(d0); d1 = ftanh(d1); d2 = ftanh(d2); d3 = ftanh(d3); }
        *(float2*)&h0[y0] = make_float2(d0, d1);
        *(float2*)&h1[y0] = make_float2(d2, d3);
    }
}

// ---------------- fc1 (tanh) + fc2 fused (3xTF32) ----------------
__global__ __launch_bounds__(512) void k_fc12_mma(const float* __restrict__ w1,
                                                  const float* __restrict__ b1,
                                                  const float* __restrict__ w2,
                                                  const float* __restrict__ b2,
                                                  float* __restrict__ out) {
    extern __shared__ unsigned sm[];
    unsigned* sHh = sm;                         // [64][BP]
    unsigned* sHl = sHh + 64 * BP;
    unsigned* sAh = sHl + 64 * BP;              // [128][AP]
    unsigned* sAl = sAh + 128 * AP;
    float* sred = (float*)(sAl + 128 * AP);     // [256]
    float* sb1  = sred + 256;                   // [128]
    float* sw2  = sb1 + 128;                    // [128]
    int x = blockIdx.x, b = blockIdx.y, tid = threadIdx.x;
    int wid = tid >> 5, lane = tid & 31, gid = lane >> 2, tig = lane & 3;
    int mt = wid & 7, nh = wid >> 3;
    int fbase = mt * 16, ybase = nh * 128;

    for (int idx = tid; idx < 128 * AP; idx += 512) {
        int f = idx / AP, c = idx % AP;
        float v = (c < 64) ? w1[c * FCN + f] : 0.f;
        split_tf(v, sAh[idx], sAl[idx]);
    }
    for (int idx = tid; idx < 64 * 64; idx += 512) {
        int i = idx >> 6, q = idx & 63;
        float4 v = *(const float4*)&g_h[(((size_t)(b * 64 + i)) * NN + x) * NN + q * 4];
        unsigned* dh = &sHh[i * BP + q * 4];
        unsigned* dl = &sHl[i * BP + q * 4];
        split_tf(v.x, dh[0], dl[0]); split_tf(v.y, dh[1], dl[1]);
        split_tf(v.z, dh[2], dl[2]); split_tf(v.w, dh[3], dl[3]);
    }
    if (tid < 256) sred[tid] = 0.f;
    if (tid < 128) { sb1[tid] = b1[tid]; sw2[tid] = w2[tid]; }
    __syncthreads();

    float bias0 = sb1[fbase + gid], bias1 = sb1[fbase + gid + 8];
    float w20 = sw2[fbase + gid], w21 = sw2[fbase + gid + 8];
    float acc[16][4];
#pragma unroll
    for (int nt = 0; nt < 16; nt++) { acc[nt][0] = acc[nt][1] = bias0; acc[nt][2] = acc[nt][3] = bias1; }

#pragma unroll
    for (int ks = 0; ks < 8; ks++) {
        int k0 = ks * 8;
        unsigned ah0 = sAh[(fbase + gid) * AP + k0 + tig];
        unsigned ah1 = sAh[(fbase + gid + 8) * AP + k0 + tig];
        unsigned ah2 = sAh[(fbase + gid) * AP + k0 + tig + 4];
        unsigned ah3 = sAh[(fbase + gid + 8) * AP + k0 + tig + 4];
        unsigned al0 = sAl[(fbase + gid) * AP + k0 + tig];
        unsigned al1 = sAl[(fbase + gid + 8) * AP + k0 + tig];
        unsigned al2 = sAl[(fbase + gid) * AP + k0 + tig + 4];
        unsigned al3 = sAl[(fbase + gid + 8) * AP + k0 + tig + 4];
#pragma unroll
        for (int nt = 0; nt < 16; nt++) {
            int n = ybase + nt * 8 + gid;
            unsigned bh0 = sHh[(k0 + tig) * BP + n];
            unsigned bh1 = sHh[(k0 + tig + 4) * BP + n];
            unsigned bl0 = sHl[(k0 + tig) * BP + n];
            unsigned bl1 = sHl[(k0 + tig + 4) * BP + n];
            MMA3(acc[nt], ah0,ah1,ah2,ah3, al0,al1,al2,al3, bh0,bh1, bl0,bl1);
        }
    }

#pragma unroll
    for (int nt = 0; nt < 16; nt++) {
        float p0 = ftanh(acc[nt][0]) * w20 + ftanh(acc[nt][2]) * w21;
        float p1 = ftanh(acc[nt][1]) * w20 + ftanh(acc[nt][3]) * w21;
#pragma unroll
        for (int m = 4; m < 32; m <<= 1) {
            p0 += __shfl_xor_sync(0xffffffffu, p0, m);
            p1 += __shfl_xor_sync(0xffffffffu, p1, m);
        }
        if (lane < 4) {
            int y0 = ybase + nt * 8 + lane * 2;
            atomicAdd(&sred[y0], p0);
            atomicAdd(&sred[y0 + 1], p1);
        }
    }
    __syncthreads();
    if (tid < 256)
        out[((size_t)b * NN + x) * NN + tid] = sred[tid] + __ldg(&b2[0]);
}

// ---------------- launch ----------------
extern "C" void kernel_launch(void* const* d_in, const int* in_sizes, int n_in,
                              void* d_out, int out_size) {
    const float* x      = (const float*)d_in[0];
    const float* fc0_w  = (const float*)d_in[1];
    const float* fc0_b  = (const float*)d_in[2];
    const float* sp_w1  = (const float*)d_in[3];
    const float* sp_w2  = (const float*)d_in[4];
    const float* conv_w = (const float*)d_in[5];
    const float* conv_b = (const float*)d_in[6];
    const float* fc1_w  = (const float*)d_in[7];
    const float* fc1_b  = (const float*)d_in[8];
    const float* fc2_w  = (const float*)d_in[9];
    const float* fc2_b  = (const float*)d_in[10];
    float* out = (float*)d_out;

    const int SM_STAGE1 = (2 * 48 * FP + 2 * 32 * BP) * 4;                              // 167424
    const int SM_ILAYER = (2 * 24 * BP + 2 * 64 * AP + 2 * 64 * 28 + 2 * 32 * BP) * 4;  // 167424
    const int SM_FC12   = (2 * 64 * BP + 2 * 128 * AP) * 4 + (256 + 128 + 128) * 4;     // 208896

    cudaFuncSetAttribute(k_stage1_mma, cudaFuncAttributeMaxDynamicSharedMemorySize, SM_STAGE1);
    cudaFuncSetAttribute(k_ilayer_mma, cudaFuncAttributeMaxDynamicSharedMemorySize, SM_ILAYER);
    cudaFuncSetAttribute(k_fc12_mma, cudaFuncAttributeMaxDynamicSharedMemorySize, SM_FC12);

    k_init<<<NN, 256>>>();
    k_wtrans<<<dim3(13, 128, LL * 2), dim3(32, 32)>>>(sp_w1, sp_w2);
    k_fc0<<<dim3(NN, BB), 256>>>(x, fc0_w, fc0_b);

    for (int l = 0; l < LL; l++) {
        k_stage1_mma<<<BB * CC, 384, SM_STAGE1>>>();
        k_stage2<<<BB * CC, 256>>>();
        k_mix<<<MODES, 256>>>(l);
        k_istage1<<<BB * CC, 256>>>();
        k_ilayer_mma<<<dim3(NN, BB), 512, SM_ILAYER>>>(conv_w, conv_b, l, (l != LL - 1) ? 1 : 0);
    }

    k_fc12_mma<<<dim3(NN, BB), 512, SM_FC12>>>(fc1_w, fc1_b, fc2_w, fc2_b, out);
}

// round 5
// speedup vs baseline: 1.2961x; 1.2961x over previous
#include <cuda_runtime.h>
#include <math.h>

#define BB 8
#define CC 64
#define NN 256
#define M1 20
#define M2 20
#define RR 40
#define MODES 800
#define LL 3
#define FCN 128
#define BP 264          // B-matrix smem row pitch (floats)
#define FP 260          // F (A) matrix pitch in stage1
#define AP 68           // A-matrix smem row pitch

// ---------------- device scratch ----------------
__device__ float g_h[BB * CC * NN * NN];
__device__ float g_spec[MODES * BB * CC];
__device__ float g_spec2[BB * CC * MODES];
__device__ float g_t2[BB * CC * NN * M2];
__device__ float g_Wm[LL * MODES * CC * CC];
__device__ float g_F1[RR * NN];
__device__ float g_F2[M2 * NN];
__device__ float g_G1[NN * RR];
__device__ float g_G2[NN * M2];

// ---------------- helpers ----------------
__device__ __forceinline__ unsigned f2tf(float f) {
    unsigned u; asm("cvt.rna.tf32.f32 %0,%1;" : "=r"(u) : "f"(f)); return u;
}
__device__ __forceinline__ void split_tf(float v, unsigned& hi, unsigned& lo) {
    unsigned h = f2tf(v);
    hi = h;
    lo = f2tf(v - __uint_as_float(h));
}
__device__ __forceinline__ void mma8(float& d0, float& d1, float& d2, float& d3,
                                     unsigned a0, unsigned a1, unsigned a2, unsigned a3,
                                     unsigned b0, unsigned b1) {
    asm("mma.sync.aligned.m16n8k8.row.col.f32.tf32.tf32.f32 "
        "{%0,%1,%2,%3},{%4,%5,%6,%7},{%8,%9},{%0,%1,%2,%3};"
        : "+f"(d0), "+f"(d1), "+f"(d2), "+f"(d3)
        : "r"(a0), "r"(a1), "r"(a2), "r"(a3), "r"(b0), "r"(b1));
}
// 3xTF32 compensated MMA: hi*lo + lo*hi + hi*hi
#define MMA3(ACC, AH0,AH1,AH2,AH3, AL0,AL1,AL2,AL3, BH0,BH1, BL0,BL1)             \
    do {                                                                           \
        mma8(ACC[0],ACC[1],ACC[2],ACC[3], AH0,AH1,AH2,AH3, BL0,BL1);               \
        mma8(ACC[0],ACC[1],ACC[2],ACC[3], AL0,AL1,AL2,AL3, BH0,BH1);               \
        mma8(ACC[0],ACC[1],ACC[2],ACC[3], AH0,AH1,AH2,AH3, BH0,BH1);               \
    } while (0)

__device__ __forceinline__ float ftanh(float x) {
    float e = __expf(2.f * x);
    return 1.f - __fdividef(2.f, e + 1.f);
}

// ---------------- DCT basis tables ----------------
__global__ void k_init() {
    int x = blockIdx.x, t = threadIdx.x;
    if (t < RR) {
        int k = (t < M1) ? t : (216 + t);
        int m = (k * x) % 510;
        float cv = (float)cospi((double)m / 255.0);
        float cx = (x == 0 || x == 255) ? 1.f : 2.f;
        g_F1[t * NN + x] = cx * cv;
        float ck = (k == 0 || k == 255) ? 1.f : 2.f;
        g_G1[x * RR + t] = ck * cv;
    }
    if (t < M2) {
        int m = (t * x) % 510;
        float cv = (float)cospi((double)m / 255.0);
        float cy = (x == 0 || x == 255) ? 1.f : 2.f;
        g_F2[t * NN + x] = cy * cv;
        float cs = (t == 0) ? 1.f : 2.f;
        g_G2[x * M2 + t] = cs * cv;
    }
}

// ---------------- spectral weight transpose ----------------
__global__ void k_wtrans(const float* __restrict__ w1, const float* __restrict__ w2) {
    __shared__ float tile[32][33];
    int l = blockIdx.z >> 1, half = blockIdx.z & 1;
    const float* src = (half ? w2 : w1) + (size_t)l * CC * CC * (M1 * M2);
    float* dst = g_Wm + ((size_t)l * MODES + half * 400) * (CC * CC);
    int col = blockIdx.x * 32 + threadIdx.x;
    int row = blockIdx.y * 32 + threadIdx.y;
    if (col < 400) tile[threadIdx.y][threadIdx.x] = src[(size_t)row * 400 + col];
    __syncthreads();
    int drow = blockIdx.x * 32 + threadIdx.y;
    int dcol = blockIdx.y * 32 + threadIdx.x;
    if (drow < 400) dst[(size_t)drow * 4096 + dcol] = tile[threadIdx.x][threadIdx.y];
}

// ---------------- fc0 ----------------
__global__ void k_fc0(const float* __restrict__ x, const float* __restrict__ w,
                      const float* __restrict__ bias) {
    __shared__ float sw[3][CC];
    __shared__ float sb[CC];
    int xi = blockIdx.x, b = blockIdx.y, y = threadIdx.x;
    if (y < CC) { sw[0][y] = w[y]; sw[1][y] = w[CC + y]; sw[2][y] = w[2 * CC + y]; sb[y] = bias[y]; }
    __syncthreads();
    const float* xp = x + (((size_t)b * NN + xi) * NN + y) * 3;
    float d0 = xp[0], d1 = xp[1], d2 = xp[2];
    float* hp = g_h + ((size_t)(b * CC) * NN + xi) * NN + y;
#pragma unroll
    for (int c = 0; c < CC; c++)
        hp[(size_t)c * (NN * NN)] = sb[c] + d0 * sw[0][c] + d1 * sw[1][c] + d2 * sw[2][c];
}

// ---------------- fused forward DCT (stage1 3xTF32 MMA + stage2 scalar) ----------------
// t1(40x256) = F1(40x256) * H(256x256) in smem; spec = t1 * F2^T
__global__ __launch_bounds__(384, 2) void k_stage12() {
    extern __shared__ float smf[];
    float* sF = smf;               // [48][FP]
    float* sH = smf + 48 * FP;     // [32][BP]
    int bc = blockIdx.x, tid = threadIdx.x;
    int wid = tid >> 5, lane = tid & 31, gid = lane >> 2, tig = lane & 3;
    int mt = wid % 3, ng = wid / 3;
    int rbase = mt * 16, ybase = ng * 64;

    for (int idx = tid; idx < 48 * NN; idx += 384) {
        int r = idx >> 8, x = idx & 255;
        sF[r * FP + x] = (r < RR) ? g_F1[r * NN + x] : 0.f;
    }
    float acc[8][4];
#pragma unroll
    for (int i = 0; i < 8; i++) { acc[i][0] = acc[i][1] = acc[i][2] = acc[i][3] = 0.f; }

    const float4* hp = (const float4*)(g_h + (size_t)bc * (NN * NN));
    for (int ch = 0; ch < 8; ch++) {
        __syncthreads();
        for (int idx = tid; idx < 32 * 64; idx += 384) {
            int row = idx >> 6, q = idx & 63;
            float4 v = hp[(ch * 32 + row) * 64 + q];
            *(float4*)&sH[row * BP + q * 4] = v;
        }
        __syncthreads();
#pragma unroll
        for (int ks = 0; ks < 4; ks++) {
            int k0 = ks * 8;
            int ca = ch * 32 + k0 + tig;
            unsigned ah0, al0, ah1, al1, ah2, al2, ah3, al3;
            split_tf(sF[(rbase + gid) * FP + ca], ah0, al0);
            split_tf(sF[(rbase + gid + 8) * FP + ca], ah1, al1);
            split_tf(sF[(rbase + gid) * FP + ca + 4], ah2, al2);
            split_tf(sF[(rbase + gid + 8) * FP + ca + 4], ah3, al3);
#pragma unroll
            for (int nt = 0; nt < 8; nt++) {
                int n = ybase + nt * 8 + gid;
                unsigned bh0, bl0, bh1, bl1;
                split_tf(sH[(k0 + tig) * BP + n], bh0, bl0);
                split_tf(sH[(k0 + tig + 4) * BP + n], bh1, bl1);
                MMA3(acc[nt], ah0,ah1,ah2,ah3, al0,al1,al2,al3, bh0,bh1, bl0,bl1);
            }
        }
    }

    // deposit t1 into smem (reuse sF region), then stage2 in-block
    __syncthreads();
    float* sT1 = smf;              // [40][256]
    int r0 = rbase + gid, r1 = r0 + 8;
#pragma unroll
    for (int nt = 0; nt < 8; nt++) {
        int y0 = ybase + nt * 8 + tig * 2;
        sT1[r0 * NN + y0] = acc[nt][0];
        sT1[r0 * NN + y0 + 1] = acc[nt][1];
        if (r1 < RR) { sT1[r1 * NN + y0] = acc[nt][2]; sT1[r1 * NN + y0 + 1] = acc[nt][3]; }
    }
    __syncthreads();

    if (tid < 200) {
        int a = tid / 5, q = tid % 5;
        float4 accv = make_float4(0.f, 0.f, 0.f, 0.f);
        const float4* F24 = (const float4*)g_F2;
        const float4* sT4 = (const float4*)sT1;
        for (int y4 = 0; y4 < 64; y4++) {
            float4 tv = sT4[a * 64 + y4];
            float4 f0 = __ldg(&F24[(4 * q + 0) * 64 + y4]);
            float4 f1 = __ldg(&F24[(4 * q + 1) * 64 + y4]);
            float4 f2 = __ldg(&F24[(4 * q + 2) * 64 + y4]);
            float4 f3 = __ldg(&F24[(4 * q + 3) * 64 + y4]);
            accv.x += tv.x * f0.x + tv.y * f0.y + tv.z * f0.z + tv.w * f0.w;
            accv.y += tv.x * f1.x + tv.y * f1.y + tv.z * f1.z + tv.w * f1.w;
            accv.z += tv.x * f2.x + tv.y * f2.y + tv.z * f2.z + tv.w * f2.w;
            accv.w += tv.x * f3.x + tv.y * f3.y + tv.z * f3.z + tv.w * f3.w;
        }
        int m0 = a * M2 + 4 * q;
        g_spec[(size_t)(m0 + 0) * (BB * CC) + bc] = accv.x;
        g_spec[(size_t)(m0 + 1) * (BB * CC) + bc] = accv.y;
        g_spec[(size_t)(m0 + 2) * (BB * CC) + bc] = accv.z;
        g_spec[(size_t)(m0 + 3) * (BB * CC) + bc] = accv.w;
    }
}

// ---------------- per-mode channel mix (exact fp32) ----------------
__global__ __launch_bounds__(256) void k_mix(int l) {
    __shared__ float sW[CC * CC];
    __shared__ float sS[BB * CC];
    int m = blockIdx.x, t = threadIdx.x;
    const float* Wp = g_Wm + ((size_t)l * MODES + m) * (CC * CC);
    for (int i = t; i < CC * CC; i += 256) sW[i] = Wp[i];
    for (int i = t; i < BB * CC; i += 256) sS[i] = g_spec[(size_t)m * (BB * CC) + i];
    __syncthreads();
#pragma unroll
    for (int k = 0; k < 2; k++) {
        int idx = t + k * 256;
        int b = idx >> 6, o = idx & 63;
        float acc = 0.f;
#pragma unroll
        for (int i = 0; i < CC; i++) acc += sS[b * CC + i] * sW[i * CC + o];
        g_spec2[(size_t)(b * CC + o) * MODES + m] = acc;
    }
}

// ---------------- inverse stage 1 (exact fp32) ----------------
__global__ __launch_bounds__(256) void k_istage1() {
    __shared__ float sS[MODES];
    int bo = blockIdx.x, x = threadIdx.x;
    for (int i = x; i < MODES; i += 256) sS[i] = g_spec2[(size_t)bo * MODES + i];
    __syncthreads();
    float g1r[RR];
    const float4* gp = (const float4*)(g_G1 + x * RR);
#pragma unroll
    for (int j = 0; j < RR / 4; j++) {
        float4 v = gp[j];
        g1r[4 * j] = v.x; g1r[4 * j + 1] = v.y; g1r[4 * j + 2] = v.z; g1r[4 * j + 3] = v.w;
    }
    float acc[M2];
#pragma unroll
    for (int s = 0; s < M2; s++) acc[s] = 0.f;
#pragma unroll 4
    for (int r = 0; r < RR; r++) {
        float g = g1r[r];
#pragma unroll
        for (int s = 0; s < M2; s++) acc[s] += g * sS[r * M2 + s];
    }
    float* tp = g_t2 + ((size_t)bo * NN + x) * M2;
#pragma unroll
    for (int s = 0; s < M2; s++) tp[s] = acc[s];
}

// ---------------- fused layer update (3xTF32, in place) ----------------
__global__ __launch_bounds__(512, 2) void k_ilayer_mma(const float* __restrict__ conv_w,
                                                       const float* __restrict__ conv_b,
                                                       int l, int do_tanh) {
    extern __shared__ float smf[];
    float* sG  = smf;                  // [24][BP]
    float* sA1 = sG + 24 * BP;         // [64][AP]
    float* sA2 = sA1 + 64 * AP;        // [64][28]
    float* sH  = sA2 + 64 * 28;        // [32][BP]
    int x = blockIdx.x, b = blockIdx.y, tid = threadIdx.x;
    int wid = tid >> 5, lane = tid & 31, gid = lane >> 2, tig = lane & 3;
    int mt = wid & 3, nh = wid >> 2;
    int obase = mt * 16, ybase = nh * 64;

    const float* cw = conv_w + (size_t)l * CC * CC;
    for (int idx = tid; idx < 64 * AP; idx += 512) {
        int o = idx / AP, i = idx % AP;
        sA1[idx] = (i < 64) ? cw[o * 64 + i] : 0.f;
    }
    for (int idx = tid; idx < 64 * 28; idx += 512) {
        int o = idx / 28, s = idx % 28;
        sA2[idx] = (s < 20) ? g_t2[(((size_t)(b * 64 + o)) * NN + x) * M2 + s] : 0.f;
    }
    for (int idx = tid; idx < 24 * NN; idx += 512) {
        int s = idx >> 8, y = idx & 255;
        sG[s * BP + y] = (s < 20) ? g_G2[y * M2 + s] : 0.f;
    }
    __syncthreads();

    float bias0 = __ldg(&conv_b[l * 64 + obase + gid]);
    float bias1 = __ldg(&conv_b[l * 64 + obase + gid + 8]);
    float acc[8][4];
#pragma unroll
    for (int nt = 0; nt < 8; nt++) { acc[nt][0] = acc[nt][1] = bias0; acc[nt][2] = acc[nt][3] = bias1; }

    // DCT term: K = 24
#pragma unroll
    for (int ks = 0; ks < 3; ks++) {
        int k0 = ks * 8;
        unsigned ah0, al0, ah1, al1, ah2, al2, ah3, al3;
        split_tf(sA2[(obase + gid) * 28 + k0 + tig], ah0, al0);
        split_tf(sA2[(obase + gid + 8) * 28 + k0 + tig], ah1, al1);
        split_tf(sA2[(obase + gid) * 28 + k0 + tig + 4], ah2, al2);
        split_tf(sA2[(obase + gid + 8) * 28 + k0 + tig + 4], ah3, al3);
#pragma unroll
        for (int nt = 0; nt < 8; nt++) {
            int n = ybase + nt * 8 + gid;
            unsigned bh0, bl0, bh1, bl1;
            split_tf(sG[(k0 + tig) * BP + n], bh0, bl0);
            split_tf(sG[(k0 + tig + 4) * BP + n], bh1, bl1);
            MMA3(acc[nt], ah0,ah1,ah2,ah3, al0,al1,al2,al3, bh0,bh1, bl0,bl1);
        }
    }

    // conv term: K = 64 in two chunks of 32
    for (int hc = 0; hc < 2; hc++) {
        __syncthreads();
        for (int idx = tid; idx < 32 * 64; idx += 512) {
            int i = idx >> 6, q = idx & 63;
            float4 v = *(const float4*)&g_h[(((size_t)(b * 64 + hc * 32 + i)) * NN + x) * NN + q * 4];
            *(float4*)&sH[i * BP + q * 4] = v;
        }
        __syncthreads();
#pragma unroll
        for (int ks = 0; ks < 4; ks++) {
            int k0 = ks * 8;
            int ca = hc * 32 + k0 + tig;
            unsigned ah0, al0, ah1, al1, ah2, al2, ah3, al3;
            split_tf(sA1[(obase + gid) * AP + ca], ah0, al0);
            split_tf(sA1[(obase + gid + 8) * AP + ca], ah1, al1);
            split_tf(sA1[(obase + gid) * AP + ca + 4], ah2, al2);
            split_tf(sA1[(obase + gid + 8) * AP + ca + 4], ah3, al3);
#pragma unroll
            for (int nt = 0; nt < 8; nt++) {
                int n = ybase + nt * 8 + gid;
                unsigned bh0, bl0, bh1, bl1;
                split_tf(sH[(k0 + tig) * BP + n], bh0, bl0);
                split_tf(sH[(k0 + tig + 4) * BP + n], bh1, bl1);
                MMA3(acc[nt], ah0,ah1,ah2,ah3, al0,al1,al2,al3, bh0,bh1, bl0,bl1);
            }
        }
    }

    int r0 = obase + gid, r1 = r0 + 8;
    float* h0 = &g_h[(((size_t)(b * 64 + r0)) * NN + x) * NN];
    float* h1 = &g_h[(((size_t)(b * 64 + r1)) * NN + x) * NN];
#pragma unroll
    for (int nt = 0; nt < 8; nt++) {
        int y0 = ybase + nt * 8 + tig * 2;
        float d0 = acc[nt][0], d1 = acc[nt][1], d2 = acc[nt][2], d3 = acc[nt][3];
        if (do_tanh) { d0 = ftanh(d0); d1 = ftanh(d1); d2 = ftanh(d2); d3 = ftanh(d3); }
        *(float2*)&h0[y0] = make_float2(d0, d1);
        *(float2*)&h1[y0] = make_float2(d2, d3);
    }
}

// ---------------- fc1 (tanh) + fc2 fused (3xTF32) ----------------
__global__ __launch_bounds__(512, 2) void k_fc12_mma(const float* __restrict__ w1,
                                                     const float* __restrict__ b1,
                                                     const float* __restrict__ w2,
                                                     const float* __restrict__ b2,
                                                     float* __restrict__ out) {
    extern __shared__ float smf[];
    float* sH = smf;                       // [64][BP]
    float* sA = sH + 64 * BP;              // [128][AP]
    float* sred = sA + 128 * AP;           // [256]
    float* sb1  = sred + 256;              // [128]
    float* sw2  = sb1 + 128;               // [128]
    int x = blockIdx.x, b = blockIdx.y, tid = threadIdx.x;
    int wid = tid >> 5, lane = tid & 31, gid = lane >> 2, tig = lane & 3;
    int mt = wid & 7, nh = wid >> 3;
    int fbase = mt * 16, ybase = nh * 128;

    for (int idx = tid; idx < 128 * AP; idx += 512) {
        int f = idx / AP, c = idx % AP;
        sA[idx] = (c < 64) ? w1[c * FCN + f] : 0.f;
    }
    for (int idx = tid; idx < 64 * 64; idx += 512) {
        int i = idx >> 6, q = idx & 63;
        float4 v = *(const float4*)&g_h[(((size_t)(b * 64 + i)) * NN + x) * NN + q * 4];
        *(float4*)&sH[i * BP + q * 4] = v;
    }
    if (tid < 256) sred[tid] = 0.f;
    if (tid < 128) { sb1[tid] = b1[tid]; sw2[tid] = w2[tid]; }
    __syncthreads();

    float bias0 = sb1[fbase + gid], bias1 = sb1[fbase + gid + 8];
    float w20 = sw2[fbase + gid], w21 = sw2[fbase + gid + 8];
    float acc[16][4];
#pragma unroll
    for (int nt = 0; nt < 16; nt++) { acc[nt][0] = acc[nt][1] = bias0; acc[nt][2] = acc[nt][3] = bias1; }

#pragma unroll
    for (int ks = 0; ks < 8; ks++) {
        int k0 = ks * 8;
        unsigned ah0, al0, ah1, al1, ah2, al2, ah3, al3;
        split_tf(sA[(fbase + gid) * AP + k0 + tig], ah0, al0);
        split_tf(sA[(fbase + gid + 8) * AP + k0 + tig], ah1, al1);
        split_tf(sA[(fbase + gid) * AP + k0 + tig + 4], ah2, al2);
        split_tf(sA[(fbase + gid + 8) * AP + k0 + tig + 4], ah3, al3);
#pragma unroll
        for (int nt = 0; nt < 16; nt++) {
            int n = ybase + nt * 8 + gid;
            unsigned bh0, bl0, bh1, bl1;
            split_tf(sH[(k0 + tig) * BP + n], bh0, bl0);
            split_tf(sH[(k0 + tig + 4) * BP + n], bh1, bl1);
            MMA3(acc[nt], ah0,ah1,ah2,ah3, al0,al1,al2,al3, bh0,bh1, bl0,bl1);
        }
    }

#pragma unroll
    for (int nt = 0; nt < 16; nt++) {
        float p0 = ftanh(acc[nt][0]) * w20 + ftanh(acc[nt][2]) * w21;
        float p1 = ftanh(acc[nt][1]) * w20 + ftanh(acc[nt][3]) * w21;
#pragma unroll
        for (int m = 4; m < 32; m <<= 1) {
            p0 += __shfl_xor_sync(0xffffffffu, p0, m);
            p1 += __shfl_xor_sync(0xffffffffu, p1, m);
        }
        if (lane < 4) {
            int y0 = ybase + nt * 8 + lane * 2;
            atomicAdd(&sred[y0], p0);
            atomicAdd(&sred[y0 + 1], p1);
        }
    }
    __syncthreads();
    if (tid < 256)
        out[((size_t)b * NN + x) * NN + tid] = sred[tid] + __ldg(&b2[0]);
}

// ---------------- launch ----------------
extern "C" void kernel_launch(void* const* d_in, const int* in_sizes, int n_in,
                              void* d_out, int out_size) {
    const float* x      = (const float*)d_in[0];
    const float* fc0_w  = (const float*)d_in[1];
    const float* fc0_b  = (const float*)d_in[2];
    const float* sp_w1  = (const float*)d_in[3];
    const float* sp_w2  = (const float*)d_in[4];
    const float* conv_w = (const float*)d_in[5];
    const float* conv_b = (const float*)d_in[6];
    const float* fc1_w  = (const float*)d_in[7];
    const float* fc1_b  = (const float*)d_in[8];
    const float* fc2_w  = (const float*)d_in[9];
    const float* fc2_b  = (const float*)d_in[10];
    float* out = (float*)d_out;

    const int SM_STAGE12 = (48 * FP + 32 * BP) * 4;                              // 83712
    const int SM_ILAYER  = (24 * BP + 64 * AP + 64 * 28 + 32 * BP) * 4;          // 83712
    const int SM_FC12    = (64 * BP + 128 * AP) * 4 + (256 + 128 + 128) * 4;     // 104448

    cudaFuncSetAttribute(k_stage12, cudaFuncAttributeMaxDynamicSharedMemorySize, SM_STAGE12);
    cudaFuncSetAttribute(k_ilayer_mma, cudaFuncAttributeMaxDynamicSharedMemorySize, SM_ILAYER);
    cudaFuncSetAttribute(k_fc12_mma, cudaFuncAttributeMaxDynamicSharedMemorySize, SM_FC12);

    k_init<<<NN, 256>>>();
    k_wtrans<<<dim3(13, 128, LL * 2), dim3(32, 32)>>>(sp_w1, sp_w2);
    k_fc0<<<dim3(NN, BB), 256>>>(x, fc0_w, fc0_b);

    for (int l = 0; l < LL; l++) {
        k_stage12<<<BB * CC, 384, SM_STAGE12>>>();
        k_mix<<<MODES, 256>>>(l);
        k_istage1<<<BB * CC, 256>>>();
        k_ilayer_mma<<<dim3(NN, BB), 512, SM_ILAYER>>>(conv_w, conv_b, l, (l != LL - 1) ? 1 : 0);
    }

    k_fc12_mma<<<dim3(NN, BB), 512, SM_FC12>>>(fc1_w, fc1_b, fc2_w, fc2_b, out);
}

// round 9
// speedup vs baseline: 1.4952x; 1.1536x over previous
#include <cuda_runtime.h>
#include <math.h>

#define BB 8
#define CC 64
#define NN 256
#define M1 20
#define M2 20
#define RR 40
#define MODES 800
#define LL 3
#define FCN 128
#define BP 264          // B-matrix smem row pitch (floats)
#define AP 68           // A-matrix smem row pitch

// ---------------- device scratch ----------------
__device__ float g_h[BB * CC * NN * NN];
__device__ float g_t1p[BB * CC * NN * M2];         // y-first DCT temp [row=(bc,x)][s]
__device__ float g_spec[MODES * BB * CC];
__device__ float g_spec2[BB * CC * MODES];
__device__ float g_t2[BB * CC * NN * M2];
__device__ float g_Wm[LL * MODES * CC * CC];
__device__ float g_F1[RR * NN];
__device__ float g_F2[M2 * NN];
__device__ float g_G1[NN * RR];
__device__ float g_G2[NN * M2];

// ---------------- helpers ----------------
__device__ __forceinline__ unsigned f2tf(float f) {
    unsigned u; asm("cvt.rna.tf32.f32 %0,%1;" : "=r"(u) : "f"(f)); return u;
}
__device__ __forceinline__ void split_tf(float v, unsigned& hi, unsigned& lo) {
    unsigned h = f2tf(v);
    hi = h;
    lo = f2tf(v - __uint_as_float(h));
}
__device__ __forceinline__ void mma8(float& d0, float& d1, float& d2, float& d3,
                                     unsigned a0, unsigned a1, unsigned a2, unsigned a3,
                                     unsigned b0, unsigned b1) {
    asm("mma.sync.aligned.m16n8k8.row.col.f32.tf32.tf32.f32 "
        "{%0,%1,%2,%3},{%4,%5,%6,%7},{%8,%9},{%0,%1,%2,%3};"
        : "+f"(d0), "+f"(d1), "+f"(d2), "+f"(d3)
        : "r"(a0), "r"(a1), "r"(a2), "r"(a3), "r"(b0), "r"(b1));
}
#define MMA3(ACC, AH0,AH1,AH2,AH3, AL0,AL1,AL2,AL3, BH0,BH1, BL0,BL1)             \
    do {                                                                           \
        mma8(ACC[0],ACC[1],ACC[2],ACC[3], AH0,AH1,AH2,AH3, BL0,BL1);               \
        mma8(ACC[0],ACC[1],ACC[2],ACC[3], AL0,AL1,AL2,AL3, BH0,BH1);               \
        mma8(ACC[0],ACC[1],ACC[2],ACC[3], AH0,AH1,AH2,AH3, BH0,BH1);               \
    } while (0)

__device__ __forceinline__ float ftanh(float x) {
    float e = __expf(2.f * x);
    return 1.f - __fdividef(2.f, e + 1.f);
}

// ---------------- DCT basis tables ----------------
__global__ void k_init() {
    int x = blockIdx.x, t = threadIdx.x;
    if (t < RR) {
        int k = (t < M1) ? t : (216 + t);
        int m = (k * x) % 510;
        float cv = (float)cospi((double)m / 255.0);
        float cx = (x == 0 || x == 255) ? 1.f : 2.f;
        g_F1[t * NN + x] = cx * cv;
        float ck = (k == 0 || k == 255) ? 1.f : 2.f;
        g_G1[x * RR + t] = ck * cv;
    }
    if (t < M2) {
        int m = (t * x) % 510;
        float cv = (float)cospi((double)m / 255.0);
        float cy = (x == 0 || x == 255) ? 1.f : 2.f;
        g_F2[t * NN + x] = cy * cv;
        float cs = (t == 0) ? 1.f : 2.f;
        g_G2[x * M2 + t] = cs * cv;
    }
}

// ---------------- spectral weight transpose ----------------
__global__ void k_wtrans(const float* __restrict__ w1, const float* __restrict__ w2) {
    __shared__ float tile[32][33];
    int l = blockIdx.z >> 1, half = blockIdx.z & 1;
    const float* src = (half ? w2 : w1) + (size_t)l * CC * CC * (M1 * M2);
    float* dst = g_Wm + ((size_t)l * MODES + half * 400) * (CC * CC);
    int col = blockIdx.x * 32 + threadIdx.x;
    int row = blockIdx.y * 32 + threadIdx.y;
    if (col < 400) tile[threadIdx.y][threadIdx.x] = src[(size_t)row * 400 + col];
    __syncthreads();
    int drow = blockIdx.x * 32 + threadIdx.y;
    int dcol = blockIdx.y * 32 + threadIdx.x;
    if (drow < 400) dst[(size_t)drow * 4096 + dcol] = tile[threadIdx.x][threadIdx.y];
}

// ---------------- fc0 ----------------
__global__ void k_fc0(const float* __restrict__ x, const float* __restrict__ w,
                      const float* __restrict__ bias) {
    __shared__ float sw[3][CC];
    __shared__ float sb[CC];
    int xi = blockIdx.x, b = blockIdx.y, y = threadIdx.x;
    if (y < CC) { sw[0][y] = w[y]; sw[1][y] = w[CC + y]; sw[2][y] = w[2 * CC + y]; sb[y] = bias[y]; }
    __syncthreads();
    const float* xp = x + (((size_t)b * NN + xi) * NN + y) * 3;
    float d0 = xp[0], d1 = xp[1], d2 = xp[2];
    float* hp = g_h + ((size_t)(b * CC) * NN + xi) * NN + y;
#pragma unroll
    for (int c = 0; c < CC; c++)
        hp[(size_t)c * (NN * NN)] = sb[c] + d0 * sw[0][c] + d1 * sw[1][c] + d2 * sw[2][c];
}

// ---------------- forward DCT stage 1' (y-first, streaming 3xTF32 GEMM) ----------------
// t1p[row][s] = sum_y H[row][y] * F2[s][y],  row = bc*256 + x  (131072 rows)
__global__ __launch_bounds__(256) void k_s1p() {
    extern __shared__ unsigned smu[];
    unsigned* sBh = smu;               // [256][24], pitch 24 -> conflict-free
    unsigned* sBl = smu + 256 * 24;
    int tid = threadIdx.x;
    int wid = tid >> 5, lane = tid & 31, gid = lane >> 2, tig = lane & 3;

    for (int idx = tid; idx < 256 * 24; idx += 256) {
        int y = idx / 24, s = idx % 24;
        float v = (s < 20) ? g_F2[s * NN + y] : 0.f;
        split_tf(v, sBh[idx], sBl[idx]);
    }
    __syncthreads();

    size_t row0 = (size_t)blockIdx.x * 128 + wid * 16;
    const float* A0 = g_h + (row0 + gid) * NN;
    const float* A1 = g_h + (row0 + gid + 8) * NN;

    float acc[3][4];
#pragma unroll
    for (int i = 0; i < 3; i++) { acc[i][0] = acc[i][1] = acc[i][2] = acc[i][3] = 0.f; }

#pragma unroll 4
    for (int k0 = 0; k0 < 256; k0 += 8) {
        float av0 = __ldg(&A0[k0 + tig]);
        float av1 = __ldg(&A1[k0 + tig]);
        float av2 = __ldg(&A0[k0 + tig + 4]);
        float av3 = __ldg(&A1[k0 + tig + 4]);
        unsigned ah0, al0, ah1, al1, ah2, al2, ah3, al3;
        split_tf(av0, ah0, al0); split_tf(av1, ah1, al1);
        split_tf(av2, ah2, al2); split_tf(av3, ah3, al3);
#pragma unroll
        for (int nt = 0; nt < 3; nt++) {
            int n = nt * 8 + gid;
            unsigned bh0 = sBh[(k0 + tig) * 24 + n];
            unsigned bh1 = sBh[(k0 + tig + 4) * 24 + n];
            unsigned bl0 = sBl[(k0 + tig) * 24 + n];
            unsigned bl1 = sBl[(k0 + tig + 4) * 24 + n];
            MMA3(acc[nt], ah0,ah1,ah2,ah3, al0,al1,al2,al3, bh0,bh1, bl0,bl1);
        }
    }

    float* t0 = g_t1p + (row0 + gid) * M2;
    float* t1 = g_t1p + (row0 + gid + 8) * M2;
#pragma unroll
    for (int nt = 0; nt < 3; nt++) {
        int c0 = nt * 8 + tig * 2;
        if (c0 < 20) {
            *(float2*)&t0[c0] = make_float2(acc[nt][0], acc[nt][1]);
            *(float2*)&t1[c0] = make_float2(acc[nt][2], acc[nt][3]);
        }
    }
}

// ---------------- forward DCT stage 2' (x contraction, exact fp32) ----------------
// spec[r][s](bc) = sum_x F1[r][x] * t1p[bc][x][s]
__global__ __launch_bounds__(256) void k_s2p() {
    __shared__ float sS[NN * M2];      // [x][s]
    int bc = blockIdx.x, t = threadIdx.x;
    const float4* tp = (const float4*)(g_t1p + (size_t)bc * NN * M2);
    for (int i = t; i < NN * 5; i += 256) ((float4*)sS)[i] = tp[i];
    __syncthreads();
    if (t < 200) {
        int a = t / 5, q = t % 5;
        float4 acc = make_float4(0.f, 0.f, 0.f, 0.f);
        const float* f1 = g_F1 + a * NN;
#pragma unroll 4
        for (int x = 0; x < NN; x++) {
            float f = __ldg(&f1[x]);
            float4 v = *(const float4*)&sS[x * M2 + 4 * q];
            acc.x += f * v.x; acc.y += f * v.y; acc.z += f * v.z; acc.w += f * v.w;
        }
        int m0 = a * M2 + 4 * q;
        g_spec[(size_t)(m0 + 0) * (BB * CC) + bc] = acc.x;
        g_spec[(size_t)(m0 + 1) * (BB * CC) + bc] = acc.y;
        g_spec[(size_t)(m0 + 2) * (BB * CC) + bc] = acc.z;
        g_spec[(size_t)(m0 + 3) * (BB * CC) + bc] = acc.w;
    }
}

// ---------------- per-mode channel mix (exact fp32) ----------------
__global__ __launch_bounds__(256) void k_mix(int l) {
    __shared__ float sW[CC * CC];
    __shared__ float sS[BB * CC];
    int m = blockIdx.x, t = threadIdx.x;
    const float* Wp = g_Wm + ((size_t)l * MODES + m) * (CC * CC);
    for (int i = t; i < CC * CC; i += 256) sW[i] = Wp[i];
    for (int i = t; i < BB * CC; i += 256) sS[i] = g_spec[(size_t)m * (BB * CC) + i];
    __syncthreads();
#pragma unroll
    for (int k = 0; k < 2; k++) {
        int idx = t + k * 256;
        int b = idx >> 6, o = idx & 63;
        float acc = 0.f;
#pragma unroll
        for (int i = 0; i < CC; i++) acc += sS[b * CC + i] * sW[i * CC + o];
        g_spec2[(size_t)(b * CC + o) * MODES + m] = acc;
    }
}

// ---------------- inverse stage 1 (exact fp32) ----------------
__global__ __launch_bounds__(256) void k_istage1() {
    __shared__ float sS[MODES];
    int bo = blockIdx.x, x = threadIdx.x;
    for (int i = x; i < MODES; i += 256) sS[i] = g_spec2[(size_t)bo * MODES + i];
    __syncthreads();
    float g1r[RR];
    const float4* gp = (const float4*)(g_G1 + x * RR);
#pragma unroll
    for (int j = 0; j < RR / 4; j++) {
        float4 v = gp[j];
        g1r[4 * j] = v.x; g1r[4 * j + 1] = v.y; g1r[4 * j + 2] = v.z; g1r[4 * j + 3] = v.w;
    }
    float acc[M2];
#pragma unroll
    for (int s = 0; s < M2; s++) acc[s] = 0.f;
#pragma unroll 4
    for (int r = 0; r < RR; r++) {
        float g = g1r[r];
#pragma unroll
        for (int s = 0; s < M2; s++) acc[s] += g * sS[r * M2 + s];
    }
    float* tp = g_t2 + ((size_t)bo * NN + x) * M2;
#pragma unroll
    for (int s = 0; s < M2; s++) tp[s] = acc[s];
}

// ---------------- fused layer update (3xTF32, in place) ----------------
__global__ __launch_bounds__(512, 2) void k_ilayer_mma(const float* __restrict__ conv_w,
                                                       const float* __restrict__ conv_b,
                                                       int l, int do_tanh) {
    extern __shared__ float smf[];
    float* sG  = smf;                  // [24][BP]
    float* sA1 = sG + 24 * BP;         // [64][AP]
    float* sA2 = sA1 + 64 * AP;        // [64][28]
    float* sH  = sA2 + 64 * 28;        // [32][BP]
    int x = blockIdx.x, b = blockIdx.y, tid = threadIdx.x;
    int wid = tid >> 5, lane = tid & 31, gid = lane >> 2, tig = lane & 3;
    int mt = wid & 3, nh = wid >> 2;
    int obase = mt * 16, ybase = nh * 64;

    const float* cw = conv_w + (size_t)l * CC * CC;
    for (int idx = tid; idx < 64 * AP; idx += 512) {
        int o = idx / AP, i = idx % AP;
        sA1[idx] = (i < 64) ? cw[o * 64 + i] : 0.f;
    }
    for (int idx = tid; idx < 64 * 28; idx += 512) {
        int o = idx / 28, s = idx % 28;
        sA2[idx] = (s < 20) ? g_t2[(((size_t)(b * 64 + o)) * NN + x) * M2 + s] : 0.f;
    }
    for (int idx = tid; idx < 24 * NN; idx += 512) {
        int s = idx >> 8, y = idx & 255;
        sG[s * BP + y] = (s < 20) ? g_G2[y * M2 + s] : 0.f;
    }
    __syncthreads();

    float bias0 = __ldg(&conv_b[l * 64 + obase + gid]);
    float bias1 = __ldg(&conv_b[l * 64 + obase + gid + 8]);
    float acc[8][4];
#pragma unroll
    for (int nt = 0; nt < 8; nt++) { acc[nt][0] = acc[nt][1] = bias0; acc[nt][2] = acc[nt][3] = bias1; }

    // DCT term: K = 24
#pragma unroll
    for (int ks = 0; ks < 3; ks++) {
        int k0 = ks * 8;
        unsigned ah0, al0, ah1, al1, ah2, al2, ah3, al3;
        split_tf(sA2[(obase + gid) * 28 + k0 + tig], ah0, al0);
        split_tf(sA2[(obase + gid + 8) * 28 + k0 + tig], ah1, al1);
        split_tf(sA2[(obase + gid) * 28 + k0 + tig + 4], ah2, al2);
        split_tf(sA2[(obase + gid + 8) * 28 + k0 + tig + 4], ah3, al3);
#pragma unroll
        for (int nt = 0; nt < 8; nt++) {
            int n = ybase + nt * 8 + gid;
            unsigned bh0, bl0, bh1, bl1;
            split_tf(sG[(k0 + tig) * BP + n], bh0, bl0);
            split_tf(sG[(k0 + tig + 4) * BP + n], bh1, bl1);
            MMA3(acc[nt], ah0,ah1,ah2,ah3, al0,al1,al2,al3, bh0,bh1, bl0,bl1);
        }
    }

    // conv term: K = 64 in two chunks of 32
    for (int hc = 0; hc < 2; hc++) {
        __syncthreads();
        for (int idx = tid; idx < 32 * 64; idx += 512) {
            int i = idx >> 6, q = idx & 63;
            float4 v = *(const float4*)&g_h[(((size_t)(b * 64 + hc * 32 + i)) * NN + x) * NN + q * 4];
            *(float4*)&sH[i * BP + q * 4] = v;
        }
        __syncthreads();
#pragma unroll
        for (int ks = 0; ks < 4; ks++) {
            int k0 = ks * 8;
            int ca = hc * 32 + k0 + tig;
            unsigned ah0, al0, ah1, al1, ah2, al2, ah3, al3;
            split_tf(sA1[(obase + gid) * AP + ca], ah0, al0);
            split_tf(sA1[(obase + gid + 8) * AP + ca], ah1, al1);
            split_tf(sA1[(obase + gid) * AP + ca + 4], ah2, al2);
            split_tf(sA1[(obase + gid + 8) * AP + ca + 4], ah3, al3);
#pragma unroll
            for (int nt = 0; nt < 8; nt++) {
                int n = ybase + nt * 8 + gid;
                unsigned bh0, bl0, bh1, bl1;
                split_tf(sH[(k0 + tig) * BP + n], bh0, bl0);
                split_tf(sH[(k0 + tig + 4) * BP + n], bh1, bl1);
                MMA3(acc[nt], ah0,ah1,ah2,ah3, al0,al1,al2,al3, bh0,bh1, bl0,bl1);
            }
        }
    }

    int r0 = obase + gid, r1 = r0 + 8;
    float* h0 = &g_h[(((size_t)(b * 64 + r0)) * NN + x) * NN];
    float* h1 = &g_h[(((size_t)(b * 64 + r1)) * NN + x) * NN];
#pragma unroll
    for (int nt = 0; nt < 8; nt++) {
        int y0 = ybase + nt * 8 + tig * 2;
        float d0 = acc[nt][0], d1 = acc[nt][1], d2 = acc[nt][2], d3 = acc[nt][3];
        if (do_tanh) { d0 = ftanh(d0); d1 = ftanh(d1); d2 = ftanh(d2); d3 = ftanh(d3); }
        *(float2*)&h0[y0] = make_float2(d0, d1);
        *(float2*)&h1[y0] = make_float2(d2, d3);
    }
}

// ---------------- fc1 (tanh) + fc2 fused (3xTF32) ----------------
__global__ __launch_bounds__(512, 2) void k_fc12_mma(const float* __restrict__ w1,
                                                     const float* __restrict__ b1,
                                                     const float* __restrict__ w2,
                                                     const float* __restrict__ b2,
                                                     float* __restrict__ out) {
    extern __shared__ float smf[];
    float* sH = smf;                       // [64][BP]
    float* sA = sH + 64 * BP;              // [128][AP]
    float* sred = sA + 128 * AP;           // [256]
    float* sb1  = sred + 256;              // [128]
    float* sw2  = sb1 + 128;               // [128]
    int x = blockIdx.x, b = blockIdx.y, tid = threadIdx.x;
    int wid = tid >> 5, lane = tid & 31, gid = lane >> 2, tig = lane & 3;
    int mt = wid & 7, nh = wid >> 3;
    int fbase = mt * 16, ybase = nh * 128;

    for (int idx = tid; idx < 128 * AP; idx += 512) {
        int f = idx / AP, c = idx % AP;
        sA[idx] = (c < 64) ? w1[c * FCN + f] : 0.f;
    }
    for (int idx = tid; idx < 64 * 64; idx += 512) {
        int i = idx >> 6, q = idx & 63;
        float4 v = *(const float4*)&g_h[(((size_t)(b * 64 + i)) * NN + x) * NN + q * 4];
        *(float4*)&sH[i * BP + q * 4] = v;
    }
    if (tid < 256) sred[tid] = 0.f;
    if (tid < 128) { sb1[tid] = b1[tid]; sw2[tid] = w2[tid]; }
    __syncthreads();

    float bias0 = sb1[fbase + gid], bias1 = sb1[fbase + gid + 8];
    float w20 = sw2[fbase + gid], w21 = sw2[fbase + gid + 8];
    float acc[16][4];
#pragma unroll
    for (int nt = 0; nt < 16; nt++) { acc[nt][0] = acc[nt][1] = bias0; acc[nt][2] = acc[nt][3] = bias1; }

#pragma unroll
    for (int ks = 0; ks < 8; ks++) {
        int k0 = ks * 8;
        unsigned ah0, al0, ah1, al1, ah2, al2, ah3, al3;
        split_tf(sA[(fbase + gid) * AP + k0 + tig], ah0, al0);
        split_tf(sA[(fbase + gid + 8) * AP + k0 + tig], ah1, al1);
        split_tf(sA[(fbase + gid) * AP + k0 + tig + 4], ah2, al2);
        split_tf(sA[(fbase + gid + 8) * AP + k0 + tig + 4], ah3, al3);
#pragma unroll
        for (int nt = 0; nt < 16; nt++) {
            int n = ybase + nt * 8 + gid;
            unsigned bh0, bl0, bh1, bl1;
            split_tf(sH[(k0 + tig) * BP + n], bh0, bl0);
            split_tf(sH[(k0 + tig + 4) * BP + n], bh1, bl1);
            MMA3(acc[nt], ah0,ah1,ah2,ah3, al0,al1,al2,al3, bh0,bh1, bl0,bl1);
        }
    }

#pragma unroll
    for (int nt = 0; nt < 16; nt++) {
        float p0 = ftanh(acc[nt][0]) * w20 + ftanh(acc[nt][2]) * w21;
        float p1 = ftanh(acc[nt][1]) * w20 + ftanh(acc[nt][3]) * w21;
#pragma unroll
        for (int m = 4; m < 32; m <<= 1) {
            p0 += __shfl_xor_sync(0xffffffffu, p0, m);
            p1 += __shfl_xor_sync(0xffffffffu, p1, m);
        }
        if (lane < 4) {
            int y0 = ybase + nt * 8 + lane * 2;
            atomicAdd(&sred[y0], p0);
            atomicAdd(&sred[y0 + 1], p1);
        }
    }
    __syncthreads();
    if (tid < 256)
        out[((size_t)b * NN + x) * NN + tid] = sred[tid] + __ldg(&b2[0]);
}

// ---------------- launch ----------------
extern "C" void kernel_launch(void* const* d_in, const int* in_sizes, int n_in,
                              void* d_out, int out_size) {
    const float* x      = (const float*)d_in[0];
    const float* fc0_w  = (const float*)d_in[1];
    const float* fc0_b  = (const float*)d_in[2];
    const float* sp_w1  = (const float*)d_in[3];
    const float* sp_w2  = (const float*)d_in[4];
    const float* conv_w = (const float*)d_in[5];
    const float* conv_b = (const float*)d_in[6];
    const float* fc1_w  = (const float*)d_in[7];
    const float* fc1_b  = (const float*)d_in[8];
    const float* fc2_w  = (const float*)d_in[9];
    const float* fc2_b  = (const float*)d_in[10];
    float* out = (float*)d_out;

    const int SM_S1P    = 2 * 256 * 24 * 4;                                      // 49152
    const int SM_ILAYER = (24 * BP + 64 * AP + 64 * 28 + 32 * BP) * 4;           // 83712
    const int SM_FC12   = (64 * BP + 128 * AP) * 4 + (256 + 128 + 128) * 4;      // 104448

    cudaFuncSetAttribute(k_s1p, cudaFuncAttributeMaxDynamicSharedMemorySize, SM_S1P);
    cudaFuncSetAttribute(k_ilayer_mma, cudaFuncAttributeMaxDynamicSharedMemorySize, SM_ILAYER);
    cudaFuncSetAttribute(k_fc12_mma, cudaFuncAttributeMaxDynamicSharedMemorySize, SM_FC12);

    k_init<<<NN, 256>>>();
    k_wtrans<<<dim3(13, 128, LL * 2), dim3(32, 32)>>>(sp_w1, sp_w2);
    k_fc0<<<dim3(NN, BB), 256>>>(x, fc0_w, fc0_b);

    for (int l = 0; l < LL; l++) {
        k_s1p<<<(BB * CC * NN) / 128, 256, SM_S1P>>>();
        k_s2p<<<BB * CC, 256>>>();
        k_mix<<<MODES, 256>>>(l);
        k_istage1<<<BB * CC, 256>>>();
        k_ilayer_mma<<<dim3(NN, BB), 512, SM_ILAYER>>>(conv_w, conv_b, l, (l != LL - 1) ? 1 : 0);
    }

    k_fc12_mma<<<dim3(NN, BB), 512, SM_FC12>>>(fc1_w, fc1_b, fc2_w, fc2_b, out);
}